// round 11
// baseline (speedup 1.0000x reference)
#include <cuda_runtime.h>
#include <cuda_bf16.h>

#define B_IMGS 64
#define CH 3
#define H_MAX 512
#define W_STRIDE 513            // stored width is W_max+1
#define OUT_H 224
#define OUT_W 224
#define SPAN 448                // max x-span of one output row's taps (step<=2.0)

__global__ __launch_bounds__(OUT_W) void center_crop_smem_kernel(
    const float* __restrict__ x, float* __restrict__ out)
{
    __shared__ float s_rows[4][CH][SPAN];   // 21504 B

    const int b   = blockIdx.y;            // 0..63
    const int oy0 = blockIdx.x * 2;        // 0,2,..,222
    const int ox  = threadIdx.x;           // 0..223
    const int tid = threadIdx.x;

    const float* img = x + (size_t)b * CH * H_MAX * W_STRIDE;

    // h at x[b,0,0,W_max], w at x[b,1,0,W_max]  (broadcast loads)
    const float h = __ldg(img + (W_STRIDE - 1));
    const float w = __ldg(img + (size_t)H_MAX * W_STRIDE + (W_STRIDE - 1));

    // ---- discrete part: bit-exact vs XLA ----
    const float min_dim = fminf(h, w);
    const float scale   = __fdiv_rn(256.0f, min_dim);   // IEEE rn
    const float h_res   = rintf(h * scale);             // half-to-even = jnp.round
    const float w_res   = rintf(w * scale);
    const float top     = rintf((h_res - (float)OUT_H) * 0.5f);
    const float left    = rintf((w_res - (float)OUT_W) * 0.5f);

    const int wi = (int)w - 1;
    const int hi = (int)h - 1;

    // helper: x tap for a given output column (uniform math, per-thread)
    auto xtap = [&](float oxf, int& x0o, int& x1o, float& wxo) {
        float sx = __fdividef(((oxf + left) + 0.5f) * w, w_res) - 0.5f;
        sx = fminf(fmaxf(sx, 0.0f), w - 1.0f);
        const float x0f = floorf(sx);
        wxo = sx - x0f;
        int x0 = min(max((int)x0f, 0), wi);
        x0o = x0;
        x1o = min(x0 + 1, wi);
    };

    // this thread's x taps
    int x0, x1; float wxv;
    xtap((float)ox, x0, x1, wxv);

    // block-uniform x-range [x_lo .. x_hi] (every thread computes identically)
    int x_lo, x_hi;
    {
        int a0, a1; float dum;
        xtap(0.0f, a0, a1, dum);
        x_lo = a0;
        xtap(223.0f, a0, a1, dum);
        x_hi = a1;
    }
    const int width = x_hi - x_lo + 1;     // <= SPAN

    // y taps for the two output rows -> 4 staged rows
    int   rows_[4];
    float wyv[2];
#pragma unroll
    for (int r = 0; r < 2; r++) {
        float sy = __fdividef((((float)(oy0 + r) + top) + 0.5f) * h, h_res) - 0.5f;
        sy = fminf(fmaxf(sy, 0.0f), h - 1.0f);
        const float y0f = floorf(sy);
        wyv[r] = sy - y0f;
        int y0 = min(max((int)y0f, 0), hi);
        rows_[2 * r]     = y0;
        rows_[2 * r + 1] = min(y0 + 1, hi);
    }

    // ---- cooperative coalesced staging: 4 rows x 3 channels x width floats ----
#pragma unroll
    for (int slot = 0; slot < 4; slot++) {
        const size_t rbase = (size_t)rows_[slot] * W_STRIDE;
#pragma unroll
        for (int c = 0; c < CH; c++) {
            const float* p = img + (size_t)c * (H_MAX * W_STRIDE) + rbase + x_lo;
            for (int j = tid; j < width; j += OUT_W) {
                s_rows[slot][c][j] = __ldg(p + j);
            }
        }
    }
    __syncthreads();

    // ---- consume from smem ----
    const int j0 = x0 - x_lo;
    const int j1 = x1 - x_lo;

    float* o = out + (((size_t)b * CH) * OUT_H + oy0) * OUT_W + ox;

#pragma unroll
    for (int c = 0; c < CH; c++) {
#pragma unroll
        for (int r = 0; r < 2; r++) {
            const float v00 = s_rows[2 * r][c][j0];
            const float v01 = s_rows[2 * r][c][j1];
            const float v10 = s_rows[2 * r + 1][c][j0];
            const float v11 = s_rows[2 * r + 1][c][j1];
            const float top_v = v00 + (v01 - v00) * wxv;
            const float bot_v = v10 + (v11 - v10) * wxv;
            o[(size_t)c * (OUT_H * OUT_W) + (size_t)r * OUT_W] =
                top_v + (bot_v - top_v) * wyv[r];
        }
    }
}

extern "C" void kernel_launch(void* const* d_in, const int* in_sizes, int n_in,
                              void* d_out, int out_size)
{
    const float* x = (const float*)d_in[0];
    float* out = (float*)d_out;
    dim3 grid(OUT_H / 2, B_IMGS);
    center_crop_smem_kernel<<<grid, OUT_W>>>(x, out);
}

// round 16
// speedup vs baseline: 1.3024x; 1.3024x over previous
#include <cuda_runtime.h>
#include <cuda_bf16.h>

#define B_IMGS 64
#define CH 3
#define H_MAX 512
#define W_STRIDE 513            // stored width is W_max+1
#define IMG_CH (H_MAX * W_STRIDE)   // 262656, divisible by 4
#define OUT_H 224
#define OUT_W 224
#define SPAN 452                // staged floats per stream (16B-aligned window)
#define SPAN4 113               // float4 count per stream

__global__ __launch_bounds__(OUT_W) void crop_stage2_kernel(
    const float* __restrict__ x, float* __restrict__ out)
{
    __shared__ __align__(16) float s[4][CH][SPAN];   // 21.7 KB

    const int b   = blockIdx.y;            // 0..63
    const int oy0 = blockIdx.x * 2;        // 0,2,..,222
    const int t   = threadIdx.x;           // 0..223

    const float* img = x + (size_t)b * CH * IMG_CH;

    // h at x[b,0,0,512], w at x[b,1,0,512]
    const float h = __ldg(img + (W_STRIDE - 1));
    const float w = __ldg(img + (size_t)IMG_CH + (W_STRIDE - 1));

    // ---- discrete part: bit-exact vs XLA ----
    const float min_dim = fminf(h, w);
    const float scale   = __fdiv_rn(256.0f, min_dim);   // IEEE rn
    const float h_res   = rintf(h * scale);             // half-to-even = jnp.round
    const float w_res   = rintf(w * scale);
    const float top     = rintf((h_res - (float)OUT_H) * 0.5f);
    const float left    = rintf((w_res - (float)OUT_W) * 0.5f);

    const int wi = (int)w - 1;
    const int hi = (int)h - 1;

    // ---- this thread's x taps ----
    float sx = __fdividef((((float)t + left) + 0.5f) * w, w_res) - 0.5f;
    sx = fminf(fmaxf(sx, 0.0f), w - 1.0f);
    const float x0f = floorf(sx);
    const float wxv = sx - x0f;
    int x0 = min(max((int)x0f, 0), wi);
    const int x1 = min(x0 + 1, wi);

    // block-uniform left edge (ox = 0)
    float sxl = __fdividef((left + 0.5f) * w, w_res) - 0.5f;
    sxl = fminf(fmaxf(sxl, 0.0f), w - 1.0f);
    const int x_lo = min(max((int)floorf(sxl), 0), wi);

    // ---- y taps for the two output rows ----
    int   srow[4];
    float wyv[2];
#pragma unroll
    for (int r = 0; r < 2; r++) {
        float sy = __fdividef((((float)(oy0 + r) + top) + 0.5f) * h, h_res) - 0.5f;
        sy = fminf(fmaxf(sy, 0.0f), h - 1.0f);
        const float y0fv = floorf(sy);
        wyv[r] = sy - y0fv;
        int y0 = min(max((int)y0fv, 0), hi);
        srow[2 * r]     = y0;
        srow[2 * r + 1] = min(y0 + 1, hi);
    }
    const bool dup = (srow[2] == srow[1]);   // block-uniform: row1's top == row0's bottom

    // ---- staging: fixed 113 float4 per stream, threads t<113, fully unrolled ----
    if (t < SPAN4) {
#pragma unroll
        for (int slot = 0; slot < 4; slot++) {
            if (slot == 2 && dup) continue;          // uniform skip
            const int row = srow[slot];
            const int a   = (row + x_lo) & 3;        // (row*513 + x_lo) % 4
            const float4* p0 = reinterpret_cast<const float4*>(
                img + (size_t)row * W_STRIDE + (x_lo - a)) + t;
#pragma unroll
            for (int c = 0; c < CH; c++) {
                const float4 v = __ldg(p0 + (size_t)c * (IMG_CH / 4));
                *reinterpret_cast<float4*>(&s[slot][c][4 * t]) = v;
            }
        }
    }
    __syncthreads();

    // ---- consume from smem ----
    const int j0b = x0 - x_lo;
    const int j1b = x1 - x_lo;
    const int slot_r1 = dup ? 1 : 2;

    // per-out-row (top slot, bottom slot, their alignment shifts)
    const int stA = 0,        sbA = 1;
    const int stB = slot_r1,  sbB = 3;
    const int aA0 = (srow[0] + x_lo) & 3;
    const int aA1 = (srow[1] + x_lo) & 3;
    const int aB0 = (srow[2] + x_lo) & 3;    // == aA1 when dup
    const int aB1 = (srow[3] + x_lo) & 3;

    float* o = out + (((size_t)b * CH) * OUT_H + oy0) * OUT_W + t;

#pragma unroll
    for (int c = 0; c < CH; c++) {
        // out row 0
        {
            const float v00 = s[stA][c][j0b + aA0];
            const float v01 = s[stA][c][j1b + aA0];
            const float v10 = s[sbA][c][j0b + aA1];
            const float v11 = s[sbA][c][j1b + aA1];
            const float tv = v00 + (v01 - v00) * wxv;
            const float bv = v10 + (v11 - v10) * wxv;
            o[(size_t)c * (OUT_H * OUT_W)] = tv + (bv - tv) * wyv[0];
        }
        // out row 1
        {
            const float v00 = s[stB][c][j0b + aB0];
            const float v01 = s[stB][c][j1b + aB0];
            const float v10 = s[sbB][c][j0b + aB1];
            const float v11 = s[sbB][c][j1b + aB1];
            const float tv = v00 + (v01 - v00) * wxv;
            const float bv = v10 + (v11 - v10) * wxv;
            o[(size_t)c * (OUT_H * OUT_W) + OUT_W] = tv + (bv - tv) * wyv[1];
        }
    }
}

extern "C" void kernel_launch(void* const* d_in, const int* in_sizes, int n_in,
                              void* d_out, int out_size)
{
    const float* x = (const float*)d_in[0];
    float* out = (float*)d_out;
    dim3 grid(OUT_H / 2, B_IMGS);
    crop_stage2_kernel<<<grid, OUT_W>>>(x, out);
}

// round 17
// speedup vs baseline: 1.8735x; 1.4385x over previous
#include <cuda_runtime.h>
#include <cuda_bf16.h>

#define B_IMGS 64
#define CH 3
#define H_MAX 512
#define W_STRIDE 513            // stored width is W_max+1
#define IMG_CH (H_MAX * W_STRIDE)
#define OUT_H 224
#define OUT_W 224
#define ROWS_PB 4

__global__ __launch_bounds__(OUT_W) void crop_dedup_kernel(
    const float* __restrict__ x, float* __restrict__ out)
{
    const int b   = blockIdx.y;                 // 0..63
    const int oy0 = blockIdx.x * ROWS_PB;       // 0,4,..,220
    const int t   = threadIdx.x;                // 0..223

    const float* img = x + (size_t)b * CH * IMG_CH;

    // h at x[b,0,0,512], w at x[b,1,0,512]  (broadcast loads)
    const float h = __ldg(img + (W_STRIDE - 1));
    const float w = __ldg(img + (size_t)IMG_CH + (W_STRIDE - 1));

    // ---- discrete part: bit-exact vs XLA ----
    const float min_dim = fminf(h, w);
    const float scale   = __fdiv_rn(256.0f, min_dim);   // IEEE rn
    const float h_res   = rintf(h * scale);             // half-to-even = jnp.round
    const float w_res   = rintf(w * scale);
    const float top     = rintf((h_res - (float)OUT_H) * 0.5f);
    const float left    = rintf((w_res - (float)OUT_W) * 0.5f);

    const int wi = (int)w - 1;
    const int hi = (int)h - 1;

    // ---- x taps (per thread) ----
    float sx = __fdividef((((float)t + left) + 0.5f) * w, w_res) - 0.5f;
    sx = fminf(fmaxf(sx, 0.0f), w - 1.0f);
    const float x0f = floorf(sx);
    const float wxv = sx - x0f;
    int x0 = min(max((int)x0f, 0), wi);
    const int x1 = min(x0 + 1, wi);

    // ---- y taps for 4 output rows (block-uniform values) ----
    int   ya[ROWS_PB], yb[ROWS_PB];
    float wyv[ROWS_PB];
#pragma unroll
    for (int r = 0; r < ROWS_PB; r++) {
        float sy = __fdividef((((float)(oy0 + r) + top) + 0.5f) * h, h_res) - 0.5f;
        sy = fminf(fmaxf(sy, 0.0f), h - 1.0f);
        const float y0fv = floorf(sy);
        wyv[r] = sy - y0fv;
        int y0 = min(max((int)y0fv, 0), hi);
        ya[r] = y0;
        yb[r] = min(y0 + 1, hi);
    }

    // uniform dedup flags
    bool eq1[ROWS_PB];   // yb[r] == ya[r]        (bottom edge clamp)
    bool eq0[ROWS_PB];   // ya[r] == yb[r-1]      (row chain overlap)
#pragma unroll
    for (int r = 0; r < ROWS_PB; r++) {
        eq1[r] = (yb[r] == ya[r]);
        eq0[r] = (r > 0) && (ya[r] == yb[r - 1]);
    }

    // row byte-offsets
    int ra[ROWS_PB], rb[ROWS_PB];
#pragma unroll
    for (int r = 0; r < ROWS_PB; r++) {
        ra[r] = ya[r] * W_STRIDE;
        rb[r] = yb[r] * W_STRIDE;
    }

    float* o = out + (((size_t)b * CH) * OUT_H + oy0) * OUT_W + t;

#pragma unroll
    for (int c = 0; c < CH; c++) {
        const float* p = img + (size_t)c * IMG_CH;
        float* oc = o + (size_t)c * (OUT_H * OUT_W);

        float pb0 = 0.0f, pb1 = 0.0f;   // previous row's bottom-tap values
#pragma unroll
        for (int r = 0; r < ROWS_PB; r++) {
            // top tap: reuse previous bottom when rows coincide (uniform pred)
            float a0, a1;
            if (eq0[r]) { a0 = pb0; a1 = pb1; }
            else        { a0 = __ldg(p + ra[r] + x0); a1 = __ldg(p + ra[r] + x1); }
            // bottom tap: reuse top when clamped (uniform pred)
            float b0, b1;
            if (eq1[r]) { b0 = a0; b1 = a1; }
            else        { b0 = __ldg(p + rb[r] + x0); b1 = __ldg(p + rb[r] + x1); }

            const float tv = a0 + (a1 - a0) * wxv;
            const float bv = b0 + (b1 - b0) * wxv;
            oc[(size_t)r * OUT_W] = tv + (bv - tv) * wyv[r];

            pb0 = b0; pb1 = b1;
        }
    }
}

extern "C" void kernel_launch(void* const* d_in, const int* in_sizes, int n_in,
                              void* d_out, int out_size)
{
    const float* x = (const float*)d_in[0];
    float* out = (float*)d_out;
    dim3 grid(OUT_H / ROWS_PB, B_IMGS);
    crop_dedup_kernel<<<grid, OUT_W>>>(x, out);
}